// round 13
// baseline (speedup 1.0000x reference)
#include <cuda_runtime.h>
#include <stdint.h>

#define NPTS 120000
#define R0PAD 120064
#define NR_TOT (R0PAD + 32768 + 4096)

// A (pre-split hi/lo) regions (u32 words)
#define OFF_L0 0ull
#define SZ_L0  (R0PAD*384ull)
#define OFF_L1 SZ_L0
#define SZ_L1  (32768ull*512ull)
#define OFF_L2 (OFF_L1 + SZ_L1)
#define SZ_L2  (4096ull*768ull)
#define VMAX_TOT (OFF_L2 + SZ_L2)

// Polar grid regions (ints)
#define GOFF0 0
#define GOFF1 691200
#define GOFF2 777600
#define GRID_TOT 788400

// Cartesian voxel-count regions (combined scan)
#define RO0 0
#define RO1 262144
#define RO2 294912
#define G_PAD 300032          // 293 * 1024

#define OUT_L0_F 33554432ull  // level-0 output floats to pre-zero

// GEMM double-buffer stage layout (u32 words)
#define STG_U32 9472          // Ah 2560 | Al 2560 | Bh 2176 | Bl 2176
#define GEMM_SMEM_B (2*STG_U32*4)

static __device__ unsigned g_Ah[VMAX_TOT];
static __device__ unsigned g_Al[VMAX_TOT];
static __device__ int      g_grid[GRID_TOT];
static __device__ int      g_p2p[3*NPTS];
static __device__ int      g_vox3[3*NPTS];
static __device__ int      g_pt[3*NPTS];
static __device__ int      g_cnts[G_PAD];
static __device__ int      g_start[G_PAD];
static __device__ int      g_cur[G_PAD];
static __device__ int      g_soccp[G_PAD];
static __device__ int      g_bsum[512];
static __device__ int      g_bsum2[512];
static __device__ int      g_list[R0PAD];
static __device__ int      g_cnt;
static __device__ unsigned g_Wh[573440];
static __device__ unsigned g_Wl[573440];

struct KnnP  { int goff, P0, P1, P2; float pv0, pv1, pv2; };
struct GsP   { int M, goff, P0, P1, P2; };
struct CntP  { int ro, D0, D1, D2; float cv0, cv1, cv2; };
struct PoolP { unsigned long long voff; int ro, C, Kc, M, L, nrows, compact; };
struct GemmP { unsigned long long out_base, voff; int woff, ro, Kc, Nc, D0, D1, D2, nb, nxb, compact; };

__device__ __forceinline__ void split_tf32(float v, unsigned& hi, unsigned& lo){
    unsigned h; asm("cvt.rna.tf32.f32 %0, %1;" : "=r"(h) : "f"(v));
    float r = v - __uint_as_float(h);
    unsigned l; asm("cvt.rna.tf32.f32 %0, %1;" : "=r"(l) : "f"(r));
    hi = h; lo = l;
}
__device__ __forceinline__ void mma_tf32(float* d, const unsigned* a, const unsigned* b){
    asm volatile(
        "mma.sync.aligned.m16n8k8.row.col.f32.tf32.tf32.f32 "
        "{%0,%1,%2,%3}, {%4,%5,%6,%7}, {%8,%9}, {%0,%1,%2,%3};\n"
        : "+f"(d[0]), "+f"(d[1]), "+f"(d[2]), "+f"(d[3])
        : "r"(a[0]), "r"(a[1]), "r"(a[2]), "r"(a[3]), "r"(b[0]), "r"(b[1]));
}
__device__ __forceinline__ void cpa16(void* dst_smem, const void* src){
    unsigned d = (unsigned)__cvta_generic_to_shared(dst_smem);
    asm volatile("cp.async.cg.shared.global [%0], [%1], 16;" :: "r"(d), "l"(src));
}
__device__ __forceinline__ float4 max4(float4 a, float4 b){
    return make_float4(fmaxf(a.x,b.x), fmaxf(a.y,b.y), fmaxf(a.z,b.z), fmaxf(a.w,b.w));
}

// Prep (zero L0 output, init grids/counts) + weight split, one launch.
__global__ void k_prep_split(float* __restrict__ out,
                             const float* __restrict__ w0, const float* __restrict__ w1,
                             const float* __restrict__ w2){
    const int no4 = (int)(OUT_L0_F >> 2);
    uint4 z = make_uint4(0u,0u,0u,0u);
    uint4* po = reinterpret_cast<uint4*>(out);
    int stride = gridDim.x*blockDim.x;
    int tid = blockIdx.x*blockDim.x + threadIdx.x;
    for (int i = tid; i < no4; i += stride) po[i] = z;
    for (int i = tid; i < GRID_TOT; i += stride) g_grid[i] = 0x7fffffff;
    for (int i = tid; i < G_PAD; i += stride) g_cnts[i] = 0;
    for (int i = tid; i < 573440; i += stride){
        float v;
        if (i < 49152)       v = w0[i];
        else if (i < 180224) v = w1[i - 49152];
        else                 v = w2[i - 180224];
        split_tf32(v, g_Wh[i], g_Wl[i]);
    }
    if (tid == 0) g_cnt = 0;
}

// Polar-grid scatter (y=0..2) + cartesian count (y=3..5), one launch.
__global__ void k_gscnt(const int* __restrict__ i0, const int* __restrict__ i1,
                        const int* __restrict__ i2, GsP s0, GsP s1, GsP s2,
                        const float* __restrict__ coord, CntP c0, CntP c1, CntP c2){
    int yv = blockIdx.y;
    int i = blockIdx.x*blockDim.x + threadIdx.x;
    if (yv < 3){
        const int* idx = (yv==0) ? i0 : (yv==1) ? i1 : i2;
        GsP s = (yv==0) ? s0 : (yv==1) ? s1 : s2;
        if (i >= s.M) return;
        int x = idx[i*4+1], y = idx[i*4+2], z = idx[i*4+3];
        if ((unsigned)x >= (unsigned)s.P0 || (unsigned)y >= (unsigned)s.P1 ||
            (unsigned)z >= (unsigned)s.P2) return;
        atomicMin(&g_grid[s.goff + (x*s.P1+y)*s.P2 + z], i);
    } else {
        int L = yv - 3;
        CntP c = (L==0) ? c0 : (L==1) ? c1 : c2;
        if (i >= NPTS) return;
        float fx = __fdiv_rn(coord[i*3+0] + 25.6f, c.cv0);
        float fy = __fdiv_rn(coord[i*3+1] + 25.6f, c.cv1);
        float fz = __fdiv_rn(coord[i*3+2] + 2.0f,  c.cv2);
        int x = min(max((int)floorf(fx), 0), c.D0-1);
        int y = min(max((int)floorf(fy), 0), c.D1-1);
        int z = min(max((int)floorf(fz), 0), c.D2-1);
        int lin = (x*c.D2 + z)*c.D1 + y;   // internal ordering: y fastest
        g_vox3[L*NPTS + i] = lin;
        atomicAdd(&g_cnts[c.ro + lin], 1);
    }
}

// Warp-cooperative exact 1-NN. One warp per (query, level). Lanes enumerate
// each Chebyshev shell's cells in parallel (flat index over the (2r+1)^3 cube,
// skipping inner cells scanned in earlier shells); per-lane running min of the
// packed key (d<<16)|idx (d < 2^20, idx < 2^16), butterfly-reduced per shell.
// Integer distances are exact; min over the pack reproduces the reference
// argmin's first-index tie-breaking. Warp-uniform break on r^2 > d_best.
__global__ void __launch_bounds__(256)
k_knn_all(const float* __restrict__ pc, KnnP q0, KnnP q1, KnnP q2){
    int L = blockIdx.y;
    KnnP p = (L==0) ? q0 : (L==1) ? q1 : q2;
    int warp = (blockIdx.x*blockDim.x + threadIdx.x) >> 5;
    int lane = threadIdx.x & 31;
    if (warp >= NPTS) return;
    int i = warp;
    const int* grid = g_grid + p.goff;
    int qx = (int)floorf(__fdiv_rn(pc[i*3+0]-0.0f,        p.pv0));
    int qy = (int)floorf(__fdiv_rn(pc[i*3+1]+3.14159274f, p.pv1));
    int qz = (int)floorf(__fdiv_rn(pc[i*3+2]+4.0f,        p.pv2));
    unsigned long long best = ~0ull;
    int rmax = p.P0 + p.P1 + p.P2;
    for (int r = 0; r <= rmax; r++){
        unsigned long long bd = best >> 16;
        if ((unsigned long long)r*(unsigned long long)r > bd) break;
        int side = 2*r + 1;
        int tot = side*side*side;
        unsigned long long lk = ~0ull;
        for (int e = lane; e < tot; e += 32){
            int dz = e % side - r;
            int rem = e / side;
            int dy = rem % side - r;
            int dx = rem / side - r;
            int ch = max(abs(dx), max(abs(dy), abs(dz)));
            if (ch != r) continue;                    // inner cells done earlier
            int x = qx + dx, y = qy + dy, z = qz + dz;
            if ((unsigned)x >= (unsigned)p.P0 || (unsigned)y >= (unsigned)p.P1 ||
                (unsigned)z >= (unsigned)p.P2) continue;
            int c = grid[(x*p.P1 + y)*p.P2 + z];
            if (c != 0x7fffffff){
                unsigned long long d = (unsigned long long)(dx*dx + dy*dy + dz*dz);
                unsigned long long key = (d << 16) | (unsigned)c;
                lk = min(lk, key);
            }
        }
        #pragma unroll
        for (int off = 16; off > 0; off >>= 1)
            lk = min(lk, __shfl_xor_sync(0xFFFFFFFFu, lk, off));
        best = min(best, lk);
    }
    if (lane == 0)
        g_p2p[L*NPTS + i] = (best == ~0ull) ? 0x7fffffff : (int)(best & 0xFFFFull);
}

// Dual scan pass 1: counts prefix AND L0-occupancy prefix (no atomics).
__global__ void k_scan1(){
    __shared__ int sh[256];
    __shared__ int sh2[256];
    int b = blockIdx.x, t = threadIdx.x;
    int base = b*1024 + t*4;
    int4 v = *reinterpret_cast<int4*>(&g_cnts[base]);
    int s = v.x+v.y+v.z+v.w;
    int isL0 = (b < 256);                  // L0 region = first 262144 cells
    int o0 = (isL0 && v.x > 0) ? 1 : 0;
    int o1 = (isL0 && v.y > 0) ? 1 : 0;
    int o2 = (isL0 && v.z > 0) ? 1 : 0;
    int o3 = (isL0 && v.w > 0) ? 1 : 0;
    int so = o0+o1+o2+o3;
    sh[t] = s; sh2[t] = so;
    __syncthreads();
    #pragma unroll
    for (int off = 1; off < 256; off <<= 1){
        int val  = (t >= off) ? sh[t-off]  : 0;
        int val2 = (t >= off) ? sh2[t-off] : 0;
        __syncthreads();
        sh[t] += val; sh2[t] += val2;
        __syncthreads();
    }
    int excl = sh[t] - s;
    g_start[base]   = excl;
    g_start[base+1] = excl + v.x;
    g_start[base+2] = excl + v.x + v.y;
    g_start[base+3] = excl + v.x + v.y + v.z;
    int excl2 = sh2[t] - so;
    g_soccp[base]   = excl2;
    g_soccp[base+1] = excl2 + o0;
    g_soccp[base+2] = excl2 + o0 + o1;
    g_soccp[base+3] = excl2 + o0 + o1 + o2;
    if (t == 255){ g_bsum[b] = sh[255]; g_bsum2[b] = sh2[255]; }
}
// Dual scan pass 2: scan block sums; also publishes total L0 occupancy (g_cnt).
__global__ void k_scan2(){
    __shared__ int sh[512];
    __shared__ int sh2[512];
    int t = threadIdx.x;
    int v  = (t < 293) ? g_bsum[t]  : 0;
    int v2 = (t < 293) ? g_bsum2[t] : 0;
    sh[t] = v; sh2[t] = v2;
    __syncthreads();
    #pragma unroll
    for (int off = 1; off < 512; off <<= 1){
        int x  = (t >= off) ? sh[t-off]  : 0;
        int x2 = (t >= off) ? sh2[t-off] : 0;
        __syncthreads();
        sh[t] += x; sh2[t] += x2;
        __syncthreads();
    }
    if (t < 293){ g_bsum[t] = sh[t] - v; g_bsum2[t] = sh2[t] - v2; }
    if (t == 292) g_cnt = sh2[292];        // total occupied L0 voxels (deterministic)
}
// Pass 3: finalize start/cur; write L0 compact list from scanned prefixes.
__global__ void k_scan3(){
    int b = blockIdx.x, t = threadIdx.x;
    int add = g_bsum[b];
    int base = b*1024 + t*4;
    int4 v = *reinterpret_cast<int4*>(&g_start[base]);
    v.x += add; v.y += add; v.z += add; v.w += add;
    *reinterpret_cast<int4*>(&g_start[base]) = v;
    *reinterpret_cast<int4*>(&g_cur[base])   = v;
    if (b < 256){
        int add2 = g_bsum2[b];
        int4 c  = *reinterpret_cast<int4*>(&g_cnts[base]);
        int4 sp = *reinterpret_cast<int4*>(&g_soccp[base]);
        if (c.x > 0) g_list[sp.x + add2] = base;
        if (c.y > 0) g_list[sp.y + add2] = base + 1;
        if (c.z > 0) g_list[sp.z + add2] = base + 2;
        if (c.w > 0) g_list[sp.w + add2] = base + 3;
    }
}

__global__ void k_ptscatter_all(){
    int L = blockIdx.y;
    int ro = (L==0) ? RO0 : (L==1) ? RO1 : RO2;
    int i = blockIdx.x*blockDim.x + threadIdx.x;
    if (i >= NPTS) return;
    int lin = g_vox3[L*NPTS + i];
    int pos = atomicAdd(&g_cur[ro + lin], 1);
    g_pt[pos] = i;
}

// Gather-based max pooling (round-9 proven shape): one 128-thread BLOCK per
// (occupied) voxel row, smem-staged ids, float4 channel groups, 2-pt unroll;
// output written pre-split (tf32 hi/lo).
__global__ void __launch_bounds__(128)
k_pool_all(const float* __restrict__ pf,
           const float* __restrict__ vf0, const float* __restrict__ vf1,
           const float* __restrict__ vf2,
           PoolP p0, PoolP p1, PoolP p2){
    int b = blockIdx.x;
    PoolP p; const float* vf;
    if (b < p0.nrows){ p = p0; vf = vf0; }
    else if (b < p0.nrows + p1.nrows){ p = p1; vf = vf1; b -= p0.nrows; }
    else { p = p2; vf = vf2; b -= p0.nrows + p1.nrows; }
    int row = b, lin;
    if (p.compact){
        if (row >= g_cnt) return;
        lin = g_list[row];
    } else lin = row;
    int s0 = g_start[p.ro + lin], s1 = g_start[p.ro + lin + 1];
    int n = s1 - s0;
    if (n <= 0) return;
    __shared__ int sp[128], spp[128];
    int t = threadIdx.x;
    const float4* pf4 = reinterpret_cast<const float4*>(pf);
    const float4* vf4 = reinterpret_cast<const float4*>(vf);
    int C4 = p.C >> 2;
    int K4 = p.Kc >> 2;                    // 96 / 128 / 192
    float4 m[2];
    float ninf = -__int_as_float(0x7f800000);
    m[0] = make_float4(ninf, ninf, ninf, ninf);
    m[1] = m[0];
    for (int c0 = 0; c0 < n; c0 += 128){
        int nc = min(128, n - c0);
        __syncthreads();
        if (t < nc){
            int i = g_pt[s0 + c0 + t];
            sp[t] = i;
            int pp = g_p2p[p.L*NPTS + i];
            spp[t] = ((unsigned)pp < (unsigned)p.M) ? pp : 0;
        }
        __syncthreads();
        int j = 0;
        for (; j + 2 <= nc; j += 2){
            int ia = sp[j],   pa = spp[j];
            int ib = sp[j+1], pb = spp[j+1];
            int q = 0;
            for (int kq = t; kq < K4; kq += 128, q++){
                float4 a = (kq < 64) ? pf4[(size_t)ia*64 + kq]
                                     : vf4[(size_t)pa*C4 + (kq-64)];
                float4 c = (kq < 64) ? pf4[(size_t)ib*64 + kq]
                                     : vf4[(size_t)pb*C4 + (kq-64)];
                m[q] = max4(m[q], max4(a, c));
            }
        }
        if (j < nc){
            int ia = sp[j], pa = spp[j];
            int q = 0;
            for (int kq = t; kq < K4; kq += 128, q++){
                float4 a = (kq < 64) ? pf4[(size_t)ia*64 + kq]
                                     : vf4[(size_t)pa*C4 + (kq-64)];
                m[q] = max4(m[q], a);
            }
        }
    }
    size_t rb = p.voff + (size_t)row * (size_t)p.Kc;
    int q = 0;
    for (int kq = t; kq < K4; kq += 128, q++){
        float4 v = m[q];
        uint4 h, l;
        split_tf32(v.x, h.x, l.x);
        split_tf32(v.y, h.y, l.y);
        split_tf32(v.z, h.z, l.z);
        split_tf32(v.w, h.w, l.w);
        *reinterpret_cast<uint4*>(&g_Ah[rb + kq*4]) = h;
        *reinterpret_cast<uint4*>(&g_Al[rb + kq*4]) = l;
    }
}

// Split-TF32 tensor-core GEMM, ALL levels in one launch, cp.async
// double-buffered. out = relu(A @ W + b), occupancy-masked, stored in
// [C*D2, D0, D1] layout.
__global__ void __launch_bounds__(256, 2)
k_gemm_all(const float* __restrict__ b0, const float* __restrict__ b1,
           const float* __restrict__ b2, float* __restrict__ out,
           GemmP q0, GemmP q1, GemmP q2){
    extern __shared__ unsigned dyn[];
    int b = blockIdx.x;
    GemmP p; const float* bias;
    if (b < q0.nb){ p = q0; bias = b0; }
    else if (b < q0.nb + q1.nb){ p = q1; bias = b1; b -= q0.nb; }
    else { p = q2; bias = b2; b -= q0.nb + q1.nb; }
    int bx = b % p.nxb, by = b / p.nxb;
    int row0 = bx * 128;
    int cnt = 0;
    if (p.compact){
        cnt = *(volatile int*)&g_cnt;
        if (row0 >= cnt) return;
    }
    __shared__ int s_ob[128];
    __shared__ int s_oc[128];

    int t = threadIdx.x;
    int lane = t & 31, wid = t >> 5;
    int warp_m = wid & 1, warp_n = wid >> 1;
    int g = lane >> 2, tg = lane & 3;
    int col0 = by * 128;
    const unsigned* gAh = g_Ah + p.voff + (size_t)row0 * (size_t)p.Kc;
    const unsigned* gAl = g_Al + p.voff + (size_t)row0 * (size_t)p.Kc;
    const unsigned* Whb = g_Wh + p.woff;
    const unsigned* Wlb = g_Wl + p.woff;
    int niter = p.Kc >> 4;

    auto stage_fill = [&](int s, int k0){
        unsigned* S  = dyn + s*STG_U32;
        unsigned* Ah = S;
        unsigned* Al = S + 2560;
        unsigned* Bh = S + 5120;
        unsigned* Bl = S + 7296;
        #pragma unroll
        for (int j = 0; j < 2; j++){
            int seg = t + j*256;
            int m   = seg >> 2;
            int si  = (seg & 3) << 2;
            size_t go = (size_t)m*p.Kc + k0 + si;
            cpa16(Ah + m*20 + si, gAh + go);
            cpa16(Al + m*20 + si, gAl + go);
        }
        #pragma unroll
        for (int j = 0; j < 2; j++){
            int seg = t + j*256;
            int kk  = seg >> 5;
            int n4  = (seg & 31) << 2;
            size_t go = (size_t)(k0+kk)*p.Nc + col0 + n4;
            cpa16(Bh + kk*136 + n4, Whb + go);
            cpa16(Bl + kk*136 + n4, Wlb + go);
        }
    };

    float acc[4][4][4];
    #pragma unroll
    for (int a = 0; a < 4; a++)
        #pragma unroll
        for (int c = 0; c < 4; c++)
            #pragma unroll
            for (int d = 0; d < 4; d++) acc[a][c][d] = 0.0f;

    stage_fill(0, 0);
    asm volatile("cp.async.commit_group;");

    for (int it = 0; it < niter; it++){
        int nxt = it + 1;
        if (nxt < niter) stage_fill(nxt & 1, nxt << 4);
        asm volatile("cp.async.commit_group;");
        asm volatile("cp.async.wait_group 1;");
        __syncthreads();

        unsigned* S  = dyn + (it & 1)*STG_U32;
        unsigned* Ah = S;
        unsigned* Al = S + 2560;
        unsigned* Bh = S + 5120;
        unsigned* Bl = S + 7296;
        #pragma unroll
        for (int ks = 0; ks < 2; ks++){
            int kk = ks << 3;
            unsigned bhf[4][2], blf[4][2];
            #pragma unroll
            for (int nt = 0; nt < 4; nt++){
                int n = warp_n*32 + nt*8 + g;
                bhf[nt][0] = Bh[(kk+tg)*136 + n];
                bhf[nt][1] = Bh[(kk+tg+4)*136 + n];
                blf[nt][0] = Bl[(kk+tg)*136 + n];
                blf[nt][1] = Bl[(kk+tg+4)*136 + n];
            }
            #pragma unroll
            for (int mt = 0; mt < 4; mt++){
                int r0 = warp_m*64 + mt*16 + g;
                unsigned ahf[4], alf[4];
                ahf[0] = Ah[(r0  )*20 + kk+tg];
                ahf[1] = Ah[(r0+8)*20 + kk+tg];
                ahf[2] = Ah[(r0  )*20 + kk+tg+4];
                ahf[3] = Ah[(r0+8)*20 + kk+tg+4];
                alf[0] = Al[(r0  )*20 + kk+tg];
                alf[1] = Al[(r0+8)*20 + kk+tg];
                alf[2] = Al[(r0  )*20 + kk+tg+4];
                alf[3] = Al[(r0+8)*20 + kk+tg+4];
                #pragma unroll
                for (int nt = 0; nt < 4; nt++){
                    mma_tf32(acc[mt][nt], ahf, bhf[nt]);
                    mma_tf32(acc[mt][nt], ahf, blf[nt]);
                    mma_tf32(acc[mt][nt], alf, bhf[nt]);
                }
            }
        }
        __syncthreads();
    }

    if (t < 128){
        int v = row0 + t;
        int lin = p.compact ? g_list[v] : v;
        int y  = lin % p.D1;
        int q  = lin / p.D1;
        int zz = q % p.D2;
        int xx = q / p.D2;
        s_ob[t] = (zz*p.D0 + xx)*p.D1 + y;
        s_oc[t] = p.compact ? (v < cnt) : (g_cnts[p.ro + v] > 0);
    }
    __syncthreads();

    size_t cstride = (size_t)p.D2 * p.D0 * p.D1;
    float* stage = reinterpret_cast<float*>(dyn);
    #pragma unroll
    for (int s = 0; s < 4; s++){
        if (warp_n == s){
            #pragma unroll
            for (int mt = 0; mt < 4; mt++){
                int r0 = warp_m*64 + mt*16 + g;
                int r1 = r0 + 8;
                int oc0 = s_oc[r0], oc1 = s_oc[r1];
                #pragma unroll
                for (int nt = 0; nt < 4; nt++){
                    int cb = nt*8 + 2*tg;
                    float bv0 = bias[col0 + s*32 + cb];
                    float bv1 = bias[col0 + s*32 + cb + 1];
                    stage[(cb  )*132 + r0] = oc0 ? fmaxf(acc[mt][nt][0] + bv0, 0.0f) : 0.0f;
                    stage[(cb+1)*132 + r0] = oc0 ? fmaxf(acc[mt][nt][1] + bv1, 0.0f) : 0.0f;
                    stage[(cb  )*132 + r1] = oc1 ? fmaxf(acc[mt][nt][2] + bv0, 0.0f) : 0.0f;
                    stage[(cb+1)*132 + r1] = oc1 ? fmaxf(acc[mt][nt][3] + bv1, 0.0f) : 0.0f;
                }
            }
        }
        __syncthreads();
        #pragma unroll
        for (int j = 0; j < 16; j++){
            int e  = t + j*256;
            int cc = e >> 7;
            int rr = e & 127;
            int c  = col0 + (s << 5) + cc;
            if (!p.compact || s_oc[rr])
                out[p.out_base + (size_t)c*cstride + s_ob[rr]] = stage[cc*132 + rr];
        }
        __syncthreads();
    }
}

extern "C" void kernel_launch(void* const* d_in, const int* in_sizes, int n_in,
                              void* d_out, int out_size){
    (void)in_sizes; (void)n_in; (void)out_size;
    const float* point_feat = (const float*)d_in[0];
    const float* p_coord    = (const float*)d_in[1];
    const float* coord      = (const float*)d_in[2];
    const int*   idxs[3] = {(const int*)d_in[4],  (const int*)d_in[8],  (const int*)d_in[12]};
    const float* vfs[3]  = {(const float*)d_in[5],(const float*)d_in[9],(const float*)d_in[13]};
    const float* Ws[3]   = {(const float*)d_in[6],(const float*)d_in[10],(const float*)d_in[14]};
    const float* bs[3]   = {(const float*)d_in[7],(const float*)d_in[11],(const float*)d_in[15]};
    float* out = (float*)d_out;

    const int Ms[3]  = {40000, 15000, 5000};
    const int Cs[3]  = {128, 256, 512};
    const int P0s[3] = {240, 120, 60}, P1s[3] = {180, 90, 45}, P2s[3] = {16, 8, 4};
    const int D0s[3] = {128, 64, 32},  D1s[3] = {128, 64, 32}, D2s[3] = {16, 8, 4};
    const int goffs[3] = {GOFF0, GOFF1, GOFF2};
    const int ros[3]   = {RO0, RO1, RO2};
    const int woffs[3] = {0, 49152, 180224};
    const size_t voffs[3] = {OFF_L0, OFF_L1, OFF_L2};
    const int nrows[3] = {R0PAD, 32768, 4096};

    const float pi  = 3.14159265358979f;
    const float r0c = 50.0f, r1c = pi + pi, r2c = 6.0f;
    const float cr0 = 25.6f + 25.6f, cr1 = cr0, cr2 = 4.4f + 2.0f;

    KnnP kp[3]; GsP gp[3]; CntP cp[3]; PoolP pp[3]; GemmP gm[3];
    size_t base = 0;
    for (int L = 0; L < 3; L++){
        float sf = (float)(2 << L);
        kp[L].goff = goffs[L];
        kp[L].P0 = P0s[L]; kp[L].P1 = P1s[L]; kp[L].P2 = P2s[L];
        kp[L].pv0 = r0c / (479.0f / sf);
        kp[L].pv1 = r1c / (359.0f / sf);
        kp[L].pv2 = r2c / (31.0f  / sf);
        gp[L].M = Ms[L]; gp[L].goff = goffs[L];
        gp[L].P0 = P0s[L]; gp[L].P1 = P1s[L]; gp[L].P2 = P2s[L];
        cp[L].ro = ros[L];
        cp[L].D0 = D0s[L]; cp[L].D1 = D1s[L]; cp[L].D2 = D2s[L];
        cp[L].cv0 = cr0 / (float)D0s[L];
        cp[L].cv1 = cr1 / (float)D1s[L];
        cp[L].cv2 = cr2 / (float)D2s[L];
        pp[L].voff = voffs[L]; pp[L].ro = ros[L];
        pp[L].C = Cs[L]; pp[L].Kc = 256 + Cs[L]; pp[L].M = Ms[L];
        pp[L].L = L; pp[L].nrows = nrows[L]; pp[L].compact = (L == 0);
        gm[L].out_base = base; gm[L].voff = voffs[L];
        gm[L].woff = woffs[L]; gm[L].ro = ros[L];
        gm[L].Kc = 256 + Cs[L]; gm[L].Nc = Cs[L];
        gm[L].D0 = D0s[L]; gm[L].D1 = D1s[L]; gm[L].D2 = D2s[L];
        gm[L].nxb = nrows[L] / 128;
        gm[L].nb  = gm[L].nxb * (Cs[L] / 128);
        gm[L].compact = (L == 0);
        base += (size_t)Cs[L] * D2s[L] * D0s[L] * D1s[L];
    }

    cudaFuncSetAttribute(k_gemm_all, cudaFuncAttributeMaxDynamicSharedMemorySize,
                         GEMM_SMEM_B);

    k_prep_split<<<1024, 256>>>(out, Ws[0], Ws[1], Ws[2]);
    k_gscnt<<<dim3((NPTS+255)/256, 6), 256>>>(idxs[0], idxs[1], idxs[2],
                                              gp[0], gp[1], gp[2],
                                              coord, cp[0], cp[1], cp[2]);
    // warp-per-query KNN: 8 warps per 256-thread block
    k_knn_all<<<dim3((NPTS+7)/8, 3), 256>>>(p_coord, kp[0], kp[1], kp[2]);
    k_scan1<<<293, 256>>>();
    k_scan2<<<1, 512>>>();
    k_scan3<<<293, 256>>>();
    k_ptscatter_all<<<dim3((NPTS+255)/256, 3), 256>>>();

    int pool_blocks = nrows[0] + nrows[1] + nrows[2];
    k_pool_all<<<pool_blocks, 128>>>(point_feat, vfs[0], vfs[1], vfs[2],
                                     pp[0], pp[1], pp[2]);
    int gemm_blocks = gm[0].nb + gm[1].nb + gm[2].nb;
    k_gemm_all<<<gemm_blocks, 256, GEMM_SMEM_B>>>(bs[0], bs[1], bs[2], out,
                                                  gm[0], gm[1], gm[2]);
}

// round 14
// speedup vs baseline: 1.0778x; 1.0778x over previous
#include <cuda_runtime.h>
#include <stdint.h>

#define NPTS 120000
#define R0PAD 120064
#define NR_TOT (R0PAD + 32768 + 4096)

// A (pre-split hi/lo) regions (u32 words)
#define OFF_L0 0ull
#define SZ_L0  (R0PAD*384ull)
#define OFF_L1 SZ_L0
#define SZ_L1  (32768ull*512ull)
#define OFF_L2 (OFF_L1 + SZ_L1)
#define SZ_L2  (4096ull*768ull)
#define VMAX_TOT (OFF_L2 + SZ_L2)

// Polar grid regions (ints)
#define GOFF0 0
#define GOFF1 691200
#define GOFF2 777600
#define GRID_TOT 788400

// Cartesian voxel-count regions (combined scan)
#define RO0 0
#define RO1 262144
#define RO2 294912
#define G_PAD 300032          // 293 * 1024

#define OUT_L0_F 33554432ull  // level-0 output floats to pre-zero

// GEMM double-buffer stage layout (u32 words)
#define STG_U32 9472          // Ah 2560 | Al 2560 | Bh 2176 | Bl 2176
#define GEMM_SMEM_B (2*STG_U32*4)

static __device__ unsigned g_Ah[VMAX_TOT];
static __device__ unsigned g_Al[VMAX_TOT];
static __device__ int      g_grid[GRID_TOT];
static __device__ int      g_p2p[3*NPTS];
static __device__ int      g_vox3[3*NPTS];
static __device__ int      g_pt[3*NPTS];
static __device__ int      g_cnts[G_PAD];
static __device__ int      g_start[G_PAD];
static __device__ int      g_cur[G_PAD];
static __device__ int      g_soccp[G_PAD];
static __device__ int      g_bsum[512];
static __device__ int      g_bsum2[512];
static __device__ int      g_list[R0PAD];
static __device__ int      g_cnt;
static __device__ unsigned g_Wh[573440];
static __device__ unsigned g_Wl[573440];

struct KnnP  { int goff, P0, P1, P2; float pv0, pv1, pv2; };
struct GsP   { int M, goff, P0, P1, P2; };
struct CntP  { int ro, D0, D1, D2; float cv0, cv1, cv2; };
struct PoolP { unsigned long long voff; int ro, C, Kc, M, L, nrows, compact; };
struct GemmP { unsigned long long out_base, voff; int woff, ro, Kc, Nc, D0, D1, D2, nb, nxb, compact; };

__device__ __forceinline__ void split_tf32(float v, unsigned& hi, unsigned& lo){
    unsigned h; asm("cvt.rna.tf32.f32 %0, %1;" : "=r"(h) : "f"(v));
    float r = v - __uint_as_float(h);
    unsigned l; asm("cvt.rna.tf32.f32 %0, %1;" : "=r"(l) : "f"(r));
    hi = h; lo = l;
}
__device__ __forceinline__ void mma_tf32(float* d, const unsigned* a, const unsigned* b){
    asm volatile(
        "mma.sync.aligned.m16n8k8.row.col.f32.tf32.tf32.f32 "
        "{%0,%1,%2,%3}, {%4,%5,%6,%7}, {%8,%9}, {%0,%1,%2,%3};\n"
        : "+f"(d[0]), "+f"(d[1]), "+f"(d[2]), "+f"(d[3])
        : "r"(a[0]), "r"(a[1]), "r"(a[2]), "r"(a[3]), "r"(b[0]), "r"(b[1]));
}
__device__ __forceinline__ void cpa16(void* dst_smem, const void* src){
    unsigned d = (unsigned)__cvta_generic_to_shared(dst_smem);
    asm volatile("cp.async.cg.shared.global [%0], [%1], 16;" :: "r"(d), "l"(src));
}
__device__ __forceinline__ float4 max4(float4 a, float4 b){
    return make_float4(fmaxf(a.x,b.x), fmaxf(a.y,b.y), fmaxf(a.z,b.z), fmaxf(a.w,b.w));
}

// Slim prep: ONLY what k_gscnt needs (grid + counts init + counter).
__global__ void k_prep(){
    int stride = gridDim.x*blockDim.x;
    int tid = blockIdx.x*blockDim.x + threadIdx.x;
    for (int i = tid; i < GRID_TOT; i += stride) g_grid[i] = 0x7fffffff;
    for (int i = tid; i < G_PAD; i += stride) g_cnts[i] = 0;
    if (tid == 0) g_cnt = 0;
}

// Polar-grid scatter (y=0..2) + cartesian count (y=3..5), one launch.
__global__ void k_gscnt(const int* __restrict__ i0, const int* __restrict__ i1,
                        const int* __restrict__ i2, GsP s0, GsP s1, GsP s2,
                        const float* __restrict__ coord, CntP c0, CntP c1, CntP c2){
    int yv = blockIdx.y;
    int i = blockIdx.x*blockDim.x + threadIdx.x;
    if (yv < 3){
        const int* idx = (yv==0) ? i0 : (yv==1) ? i1 : i2;
        GsP s = (yv==0) ? s0 : (yv==1) ? s1 : s2;
        if (i >= s.M) return;
        int x = idx[i*4+1], y = idx[i*4+2], z = idx[i*4+3];
        if ((unsigned)x >= (unsigned)s.P0 || (unsigned)y >= (unsigned)s.P1 ||
            (unsigned)z >= (unsigned)s.P2) return;
        atomicMin(&g_grid[s.goff + (x*s.P1+y)*s.P2 + z], i);
    } else {
        int L = yv - 3;
        CntP c = (L==0) ? c0 : (L==1) ? c1 : c2;
        if (i >= NPTS) return;
        float fx = __fdiv_rn(coord[i*3+0] + 25.6f, c.cv0);
        float fy = __fdiv_rn(coord[i*3+1] + 25.6f, c.cv1);
        float fz = __fdiv_rn(coord[i*3+2] + 2.0f,  c.cv2);
        int x = min(max((int)floorf(fx), 0), c.D0-1);
        int y = min(max((int)floorf(fy), 0), c.D1-1);
        int z = min(max((int)floorf(fz), 0), c.D2-1);
        int lin = (x*c.D2 + z)*c.D1 + y;   // internal ordering: y fastest
        g_vox3[L*NPTS + i] = lin;
        atomicAdd(&g_cnts[c.ro + lin], 1);
    }
}

__device__ __forceinline__ void knn_check(const int* __restrict__ grid,
                                          int x,int y,int z,int qx,int qy,int qz,
                                          int P1,int P2,int& bd,int& bi){
    int c = grid[(x*P1+y)*P2 + z];
    if (c != 0x7fffffff){
        int dx = x-qx, dy = y-qy, dz = z-qz;
        int d = dx*dx + dy*dy + dz*dz;
        if (d < bd || (d == bd && c < bi)){ bd = d; bi = c; }
    }
}

// Exact 1-NN (round-12 proven thread-per-query shape), 3 levels concurrent
// (blockIdx.y 0..2). blockIdx.y == 3: co-scheduled bandwidth work — zero the
// L0 output region and split the weights to TF32 hi/lo. The KNN blocks are
// latency-bound (DRAM 0.7%), the y=3 blocks pure-bandwidth: they overlap.
__global__ void k_knn_all(const float* __restrict__ pc, KnnP q0, KnnP q1, KnnP q2,
                          float* __restrict__ out,
                          const float* __restrict__ w0, const float* __restrict__ w1,
                          const float* __restrict__ w2){
    int L = blockIdx.y;
    if (L == 3){
        const int no4 = (int)(OUT_L0_F >> 2);
        uint4 z = make_uint4(0u,0u,0u,0u);
        uint4* po = reinterpret_cast<uint4*>(out);
        int stride = gridDim.x*blockDim.x;
        int tid = blockIdx.x*blockDim.x + threadIdx.x;
        for (int i = tid; i < no4; i += stride) po[i] = z;
        for (int i = tid; i < 573440; i += stride){
            float v;
            if (i < 49152)       v = w0[i];
            else if (i < 180224) v = w1[i - 49152];
            else                 v = w2[i - 180224];
            split_tf32(v, g_Wh[i], g_Wl[i]);
        }
        return;
    }
    KnnP p = (L==0) ? q0 : (L==1) ? q1 : q2;
    int i = blockIdx.x*blockDim.x + threadIdx.x;
    if (i >= NPTS) return;
    const int* grid = g_grid + p.goff;
    int qx = (int)floorf(__fdiv_rn(pc[i*3+0]-0.0f,        p.pv0));
    int qy = (int)floorf(__fdiv_rn(pc[i*3+1]+3.14159274f, p.pv1));
    int qz = (int)floorf(__fdiv_rn(pc[i*3+2]+4.0f,        p.pv2));
    int bd = 0x7fffffff, bi = 0x7fffffff;
    int rmax = p.P0 + p.P1 + p.P2;
    for (int r = 0; r <= rmax; r++){
        if ((long long)r*r > (long long)bd) break;
        int x0 = max(qx-r, 0), x1 = min(qx+r, p.P0-1);
        int y0 = max(qy-r, 0), y1 = min(qy+r, p.P1-1);
        int z0 = max(qz-r, 0), z1 = min(qz+r, p.P2-1);
        for (int x = x0; x <= x1; x++){
            bool fx = (x == qx-r) || (x == qx+r);
            for (int y = y0; y <= y1; y++){
                bool fy = (y == qy-r) || (y == qy+r);
                if (fx | fy){
                    for (int z = z0; z <= z1; z++)
                        knn_check(grid,x,y,z,qx,qy,qz,p.P1,p.P2,bd,bi);
                } else {
                    int za = qz - r;
                    if (za >= 0 && za < p.P2) knn_check(grid,x,y,za,qx,qy,qz,p.P1,p.P2,bd,bi);
                    int zb = qz + r;
                    if (r > 0 && zb >= 0 && zb < p.P2) knn_check(grid,x,y,zb,qx,qy,qz,p.P1,p.P2,bd,bi);
                }
            }
        }
    }
    g_p2p[L*NPTS + i] = bi;
}

// Dual scan pass 1: counts prefix AND L0-occupancy prefix (no atomics).
__global__ void k_scan1(){
    __shared__ int sh[256];
    __shared__ int sh2[256];
    int b = blockIdx.x, t = threadIdx.x;
    int base = b*1024 + t*4;
    int4 v = *reinterpret_cast<int4*>(&g_cnts[base]);
    int s = v.x+v.y+v.z+v.w;
    int isL0 = (b < 256);                  // L0 region = first 262144 cells
    int o0 = (isL0 && v.x > 0) ? 1 : 0;
    int o1 = (isL0 && v.y > 0) ? 1 : 0;
    int o2 = (isL0 && v.z > 0) ? 1 : 0;
    int o3 = (isL0 && v.w > 0) ? 1 : 0;
    int so = o0+o1+o2+o3;
    sh[t] = s; sh2[t] = so;
    __syncthreads();
    #pragma unroll
    for (int off = 1; off < 256; off <<= 1){
        int val  = (t >= off) ? sh[t-off]  : 0;
        int val2 = (t >= off) ? sh2[t-off] : 0;
        __syncthreads();
        sh[t] += val; sh2[t] += val2;
        __syncthreads();
    }
    int excl = sh[t] - s;
    g_start[base]   = excl;
    g_start[base+1] = excl + v.x;
    g_start[base+2] = excl + v.x + v.y;
    g_start[base+3] = excl + v.x + v.y + v.z;
    int excl2 = sh2[t] - so;
    g_soccp[base]   = excl2;
    g_soccp[base+1] = excl2 + o0;
    g_soccp[base+2] = excl2 + o0 + o1;
    g_soccp[base+3] = excl2 + o0 + o1 + o2;
    if (t == 255){ g_bsum[b] = sh[255]; g_bsum2[b] = sh2[255]; }
}
// Dual scan pass 2: scan block sums; also publishes total L0 occupancy (g_cnt).
__global__ void k_scan2(){
    __shared__ int sh[512];
    __shared__ int sh2[512];
    int t = threadIdx.x;
    int v  = (t < 293) ? g_bsum[t]  : 0;
    int v2 = (t < 293) ? g_bsum2[t] : 0;
    sh[t] = v; sh2[t] = v2;
    __syncthreads();
    #pragma unroll
    for (int off = 1; off < 512; off <<= 1){
        int x  = (t >= off) ? sh[t-off]  : 0;
        int x2 = (t >= off) ? sh2[t-off] : 0;
        __syncthreads();
        sh[t] += x; sh2[t] += x2;
        __syncthreads();
    }
    if (t < 293){ g_bsum[t] = sh[t] - v; g_bsum2[t] = sh2[t] - v2; }
    if (t == 292) g_cnt = sh2[292];        // total occupied L0 voxels (deterministic)
}
// Pass 3: finalize start/cur; write L0 compact list from scanned prefixes.
__global__ void k_scan3(){
    int b = blockIdx.x, t = threadIdx.x;
    int add = g_bsum[b];
    int base = b*1024 + t*4;
    int4 v = *reinterpret_cast<int4*>(&g_start[base]);
    v.x += add; v.y += add; v.z += add; v.w += add;
    *reinterpret_cast<int4*>(&g_start[base]) = v;
    *reinterpret_cast<int4*>(&g_cur[base])   = v;
    if (b < 256){
        int add2 = g_bsum2[b];
        int4 c  = *reinterpret_cast<int4*>(&g_cnts[base]);
        int4 sp = *reinterpret_cast<int4*>(&g_soccp[base]);
        if (c.x > 0) g_list[sp.x + add2] = base;
        if (c.y > 0) g_list[sp.y + add2] = base + 1;
        if (c.z > 0) g_list[sp.z + add2] = base + 2;
        if (c.w > 0) g_list[sp.w + add2] = base + 3;
    }
}

__global__ void k_ptscatter_all(){
    int L = blockIdx.y;
    int ro = (L==0) ? RO0 : (L==1) ? RO1 : RO2;
    int i = blockIdx.x*blockDim.x + threadIdx.x;
    if (i >= NPTS) return;
    int lin = g_vox3[L*NPTS + i];
    int pos = atomicAdd(&g_cur[ro + lin], 1);
    g_pt[pos] = i;
}

// Gather-based max pooling (round-9 proven shape): one 128-thread BLOCK per
// (occupied) voxel row, smem-staged ids, float4 channel groups, 2-pt unroll;
// output written pre-split (tf32 hi/lo).
__global__ void __launch_bounds__(128)
k_pool_all(const float* __restrict__ pf,
           const float* __restrict__ vf0, const float* __restrict__ vf1,
           const float* __restrict__ vf2,
           PoolP p0, PoolP p1, PoolP p2){
    int b = blockIdx.x;
    PoolP p; const float* vf;
    if (b < p0.nrows){ p = p0; vf = vf0; }
    else if (b < p0.nrows + p1.nrows){ p = p1; vf = vf1; b -= p0.nrows; }
    else { p = p2; vf = vf2; b -= p0.nrows + p1.nrows; }
    int row = b, lin;
    if (p.compact){
        if (row >= g_cnt) return;
        lin = g_list[row];
    } else lin = row;
    int s0 = g_start[p.ro + lin], s1 = g_start[p.ro + lin + 1];
    int n = s1 - s0;
    if (n <= 0) return;
    __shared__ int sp[128], spp[128];
    int t = threadIdx.x;
    const float4* pf4 = reinterpret_cast<const float4*>(pf);
    const float4* vf4 = reinterpret_cast<const float4*>(vf);
    int C4 = p.C >> 2;
    int K4 = p.Kc >> 2;                    // 96 / 128 / 192
    float4 m[2];
    float ninf = -__int_as_float(0x7f800000);
    m[0] = make_float4(ninf, ninf, ninf, ninf);
    m[1] = m[0];
    for (int c0 = 0; c0 < n; c0 += 128){
        int nc = min(128, n - c0);
        __syncthreads();
        if (t < nc){
            int i = g_pt[s0 + c0 + t];
            sp[t] = i;
            int pp = g_p2p[p.L*NPTS + i];
            spp[t] = ((unsigned)pp < (unsigned)p.M) ? pp : 0;
        }
        __syncthreads();
        int j = 0;
        for (; j + 2 <= nc; j += 2){
            int ia = sp[j],   pa = spp[j];
            int ib = sp[j+1], pb = spp[j+1];
            int q = 0;
            for (int kq = t; kq < K4; kq += 128, q++){
                float4 a = (kq < 64) ? pf4[(size_t)ia*64 + kq]
                                     : vf4[(size_t)pa*C4 + (kq-64)];
                float4 c = (kq < 64) ? pf4[(size_t)ib*64 + kq]
                                     : vf4[(size_t)pb*C4 + (kq-64)];
                m[q] = max4(m[q], max4(a, c));
            }
        }
        if (j < nc){
            int ia = sp[j], pa = spp[j];
            int q = 0;
            for (int kq = t; kq < K4; kq += 128, q++){
                float4 a = (kq < 64) ? pf4[(size_t)ia*64 + kq]
                                     : vf4[(size_t)pa*C4 + (kq-64)];
                m[q] = max4(m[q], a);
            }
        }
    }
    size_t rb = p.voff + (size_t)row * (size_t)p.Kc;
    int q = 0;
    for (int kq = t; kq < K4; kq += 128, q++){
        float4 v = m[q];
        uint4 h, l;
        split_tf32(v.x, h.x, l.x);
        split_tf32(v.y, h.y, l.y);
        split_tf32(v.z, h.z, l.z);
        split_tf32(v.w, h.w, l.w);
        *reinterpret_cast<uint4*>(&g_Ah[rb + kq*4]) = h;
        *reinterpret_cast<uint4*>(&g_Al[rb + kq*4]) = l;
    }
}

// Split-TF32 tensor-core GEMM, ALL levels in one launch, cp.async
// double-buffered. out = relu(A @ W + b), occupancy-masked, stored in
// [C*D2, D0, D1] layout.
__global__ void __launch_bounds__(256, 2)
k_gemm_all(const float* __restrict__ b0, const float* __restrict__ b1,
           const float* __restrict__ b2, float* __restrict__ out,
           GemmP q0, GemmP q1, GemmP q2){
    extern __shared__ unsigned dyn[];
    int b = blockIdx.x;
    GemmP p; const float* bias;
    if (b < q0.nb){ p = q0; bias = b0; }
    else if (b < q0.nb + q1.nb){ p = q1; bias = b1; b -= q0.nb; }
    else { p = q2; bias = b2; b -= q0.nb + q1.nb; }
    int bx = b % p.nxb, by = b / p.nxb;
    int row0 = bx * 128;
    int cnt = 0;
    if (p.compact){
        cnt = *(volatile int*)&g_cnt;
        if (row0 >= cnt) return;
    }
    __shared__ int s_ob[128];
    __shared__ int s_oc[128];

    int t = threadIdx.x;
    int lane = t & 31, wid = t >> 5;
    int warp_m = wid & 1, warp_n = wid >> 1;
    int g = lane >> 2, tg = lane & 3;
    int col0 = by * 128;
    const unsigned* gAh = g_Ah + p.voff + (size_t)row0 * (size_t)p.Kc;
    const unsigned* gAl = g_Al + p.voff + (size_t)row0 * (size_t)p.Kc;
    const unsigned* Whb = g_Wh + p.woff;
    const unsigned* Wlb = g_Wl + p.woff;
    int niter = p.Kc >> 4;

    auto stage_fill = [&](int s, int k0){
        unsigned* S  = dyn + s*STG_U32;
        unsigned* Ah = S;
        unsigned* Al = S + 2560;
        unsigned* Bh = S + 5120;
        unsigned* Bl = S + 7296;
        #pragma unroll
        for (int j = 0; j < 2; j++){
            int seg = t + j*256;
            int m   = seg >> 2;
            int si  = (seg & 3) << 2;
            size_t go = (size_t)m*p.Kc + k0 + si;
            cpa16(Ah + m*20 + si, gAh + go);
            cpa16(Al + m*20 + si, gAl + go);
        }
        #pragma unroll
        for (int j = 0; j < 2; j++){
            int seg = t + j*256;
            int kk  = seg >> 5;
            int n4  = (seg & 31) << 2;
            size_t go = (size_t)(k0+kk)*p.Nc + col0 + n4;
            cpa16(Bh + kk*136 + n4, Whb + go);
            cpa16(Bl + kk*136 + n4, Wlb + go);
        }
    };

    float acc[4][4][4];
    #pragma unroll
    for (int a = 0; a < 4; a++)
        #pragma unroll
        for (int c = 0; c < 4; c++)
            #pragma unroll
            for (int d = 0; d < 4; d++) acc[a][c][d] = 0.0f;

    stage_fill(0, 0);
    asm volatile("cp.async.commit_group;");

    for (int it = 0; it < niter; it++){
        int nxt = it + 1;
        if (nxt < niter) stage_fill(nxt & 1, nxt << 4);
        asm volatile("cp.async.commit_group;");
        asm volatile("cp.async.wait_group 1;");
        __syncthreads();

        unsigned* S  = dyn + (it & 1)*STG_U32;
        unsigned* Ah = S;
        unsigned* Al = S + 2560;
        unsigned* Bh = S + 5120;
        unsigned* Bl = S + 7296;
        #pragma unroll
        for (int ks = 0; ks < 2; ks++){
            int kk = ks << 3;
            unsigned bhf[4][2], blf[4][2];
            #pragma unroll
            for (int nt = 0; nt < 4; nt++){
                int n = warp_n*32 + nt*8 + g;
                bhf[nt][0] = Bh[(kk+tg)*136 + n];
                bhf[nt][1] = Bh[(kk+tg+4)*136 + n];
                blf[nt][0] = Bl[(kk+tg)*136 + n];
                blf[nt][1] = Bl[(kk+tg+4)*136 + n];
            }
            #pragma unroll
            for (int mt = 0; mt < 4; mt++){
                int r0 = warp_m*64 + mt*16 + g;
                unsigned ahf[4], alf[4];
                ahf[0] = Ah[(r0  )*20 + kk+tg];
                ahf[1] = Ah[(r0+8)*20 + kk+tg];
                ahf[2] = Ah[(r0  )*20 + kk+tg+4];
                ahf[3] = Ah[(r0+8)*20 + kk+tg+4];
                alf[0] = Al[(r0  )*20 + kk+tg];
                alf[1] = Al[(r0+8)*20 + kk+tg];
                alf[2] = Al[(r0  )*20 + kk+tg+4];
                alf[3] = Al[(r0+8)*20 + kk+tg+4];
                #pragma unroll
                for (int nt = 0; nt < 4; nt++){
                    mma_tf32(acc[mt][nt], ahf, bhf[nt]);
                    mma_tf32(acc[mt][nt], ahf, blf[nt]);
                    mma_tf32(acc[mt][nt], alf, bhf[nt]);
                }
            }
        }
        __syncthreads();
    }

    if (t < 128){
        int v = row0 + t;
        int lin = p.compact ? g_list[v] : v;
        int y  = lin % p.D1;
        int q  = lin / p.D1;
        int zz = q % p.D2;
        int xx = q / p.D2;
        s_ob[t] = (zz*p.D0 + xx)*p.D1 + y;
        s_oc[t] = p.compact ? (v < cnt) : (g_cnts[p.ro + v] > 0);
    }
    __syncthreads();

    size_t cstride = (size_t)p.D2 * p.D0 * p.D1;
    float* stage = reinterpret_cast<float*>(dyn);
    #pragma unroll
    for (int s = 0; s < 4; s++){
        if (warp_n == s){
            #pragma unroll
            for (int mt = 0; mt < 4; mt++){
                int r0 = warp_m*64 + mt*16 + g;
                int r1 = r0 + 8;
                int oc0 = s_oc[r0], oc1 = s_oc[r1];
                #pragma unroll
                for (int nt = 0; nt < 4; nt++){
                    int cb = nt*8 + 2*tg;
                    float bv0 = bias[col0 + s*32 + cb];
                    float bv1 = bias[col0 + s*32 + cb + 1];
                    stage[(cb  )*132 + r0] = oc0 ? fmaxf(acc[mt][nt][0] + bv0, 0.0f) : 0.0f;
                    stage[(cb+1)*132 + r0] = oc0 ? fmaxf(acc[mt][nt][1] + bv1, 0.0f) : 0.0f;
                    stage[(cb  )*132 + r1] = oc1 ? fmaxf(acc[mt][nt][2] + bv0, 0.0f) : 0.0f;
                    stage[(cb+1)*132 + r1] = oc1 ? fmaxf(acc[mt][nt][3] + bv1, 0.0f) : 0.0f;
                }
            }
        }
        __syncthreads();
        #pragma unroll
        for (int j = 0; j < 16; j++){
            int e  = t + j*256;
            int cc = e >> 7;
            int rr = e & 127;
            int c  = col0 + (s << 5) + cc;
            if (!p.compact || s_oc[rr])
                out[p.out_base + (size_t)c*cstride + s_ob[rr]] = stage[cc*132 + rr];
        }
        __syncthreads();
    }
}

extern "C" void kernel_launch(void* const* d_in, const int* in_sizes, int n_in,
                              void* d_out, int out_size){
    (void)in_sizes; (void)n_in; (void)out_size;
    const float* point_feat = (const float*)d_in[0];
    const float* p_coord    = (const float*)d_in[1];
    const float* coord      = (const float*)d_in[2];
    const int*   idxs[3] = {(const int*)d_in[4],  (const int*)d_in[8],  (const int*)d_in[12]};
    const float* vfs[3]  = {(const float*)d_in[5],(const float*)d_in[9],(const float*)d_in[13]};
    const float* Ws[3]   = {(const float*)d_in[6],(const float*)d_in[10],(const float*)d_in[14]};
    const float* bs[3]   = {(const float*)d_in[7],(const float*)d_in[11],(const float*)d_in[15]};
    float* out = (float*)d_out;

    const int Ms[3]  = {40000, 15000, 5000};
    const int Cs[3]  = {128, 256, 512};
    const int P0s[3] = {240, 120, 60}, P1s[3] = {180, 90, 45}, P2s[3] = {16, 8, 4};
    const int D0s[3] = {128, 64, 32},  D1s[3] = {128, 64, 32}, D2s[3] = {16, 8, 4};
    const int goffs[3] = {GOFF0, GOFF1, GOFF2};
    const int ros[3]   = {RO0, RO1, RO2};
    const int woffs[3] = {0, 49152, 180224};
    const size_t voffs[3] = {OFF_L0, OFF_L1, OFF_L2};
    const int nrows[3] = {R0PAD, 32768, 4096};

    const float pi  = 3.14159265358979f;
    const float r0c = 50.0f, r1c = pi + pi, r2c = 6.0f;
    const float cr0 = 25.6f + 25.6f, cr1 = cr0, cr2 = 4.4f + 2.0f;

    KnnP kp[3]; GsP gp[3]; CntP cp[3]; PoolP pp[3]; GemmP gm[3];
    size_t base = 0;
    for (int L = 0; L < 3; L++){
        float sf = (float)(2 << L);
        kp[L].goff = goffs[L];
        kp[L].P0 = P0s[L]; kp[L].P1 = P1s[L]; kp[L].P2 = P2s[L];
        kp[L].pv0 = r0c / (479.0f / sf);
        kp[L].pv1 = r1c / (359.0f / sf);
        kp[L].pv2 = r2c / (31.0f  / sf);
        gp[L].M = Ms[L]; gp[L].goff = goffs[L];
        gp[L].P0 = P0s[L]; gp[L].P1 = P1s[L]; gp[L].P2 = P2s[L];
        cp[L].ro = ros[L];
        cp[L].D0 = D0s[L]; cp[L].D1 = D1s[L]; cp[L].D2 = D2s[L];
        cp[L].cv0 = cr0 / (float)D0s[L];
        cp[L].cv1 = cr1 / (float)D1s[L];
        cp[L].cv2 = cr2 / (float)D2s[L];
        pp[L].voff = voffs[L]; pp[L].ro = ros[L];
        pp[L].C = Cs[L]; pp[L].Kc = 256 + Cs[L]; pp[L].M = Ms[L];
        pp[L].L = L; pp[L].nrows = nrows[L]; pp[L].compact = (L == 0);
        gm[L].out_base = base; gm[L].voff = voffs[L];
        gm[L].woff = woffs[L]; gm[L].ro = ros[L];
        gm[L].Kc = 256 + Cs[L]; gm[L].Nc = Cs[L];
        gm[L].D0 = D0s[L]; gm[L].D1 = D1s[L]; gm[L].D2 = D2s[L];
        gm[L].nxb = nrows[L] / 128;
        gm[L].nb  = gm[L].nxb * (Cs[L] / 128);
        gm[L].compact = (L == 0);
        base += (size_t)Cs[L] * D2s[L] * D0s[L] * D1s[L];
    }

    cudaFuncSetAttribute(k_gemm_all, cudaFuncAttributeMaxDynamicSharedMemorySize,
                         GEMM_SMEM_B);

    k_prep<<<512, 256>>>();
    k_gscnt<<<dim3((NPTS+255)/256, 6), 256>>>(idxs[0], idxs[1], idxs[2],
                                              gp[0], gp[1], gp[2],
                                              coord, cp[0], cp[1], cp[2]);
    // KNN (y=0..2, thread-per-query) + co-scheduled zero/splitW (y=3)
    k_knn_all<<<dim3((NPTS+127)/128, 4), 128>>>(p_coord, kp[0], kp[1], kp[2],
                                                out, Ws[0], Ws[1], Ws[2]);
    k_scan1<<<293, 256>>>();
    k_scan2<<<1, 512>>>();
    k_scan3<<<293, 256>>>();
    k_ptscatter_all<<<dim3((NPTS+255)/256, 3), 256>>>();

    int pool_blocks = nrows[0] + nrows[1] + nrows[2];
    k_pool_all<<<pool_blocks, 128>>>(point_feat, vfs[0], vfs[1], vfs[2],
                                     pp[0], pp[1], pp[2]);
    int gemm_blocks = gm[0].nb + gm[1].nb + gm[2].nb;
    k_gemm_all<<<gemm_blocks, 256, GEMM_SMEM_B>>>(bs[0], bs[1], bs[2], out,
                                                  gm[0], gm[1], gm[2]);
}

// round 15
// speedup vs baseline: 1.1634x; 1.0795x over previous
#include <cuda_runtime.h>
#include <stdint.h>

#define NPTS 120000
#define R0PAD 120064
#define NR_TOT (R0PAD + 32768 + 4096)

// A (float) regions (f32 words)
#define OFF_L0 0ull
#define SZ_L0  (R0PAD*384ull)
#define OFF_L1 SZ_L0
#define SZ_L1  (32768ull*512ull)
#define OFF_L2 (OFF_L1 + SZ_L1)
#define SZ_L2  (4096ull*768ull)
#define VMAX_TOT (OFF_L2 + SZ_L2)

// Polar grid regions (ints)
#define GOFF0 0
#define GOFF1 691200
#define GOFF2 777600
#define GRID_TOT 788400

// Cartesian voxel-count regions (combined scan)
#define RO0 0
#define RO1 262144
#define RO2 294912
#define G_PAD 300032          // 293 * 1024

#define OUT_L0_F 33554432ull  // level-0 output floats to pre-zero

// GEMM double-buffer stage layout (u32 words): Af 2560 | Bh 2176 | Bl 2176
#define STG_U32 6912
#define GEMM_SMEM_B (2*STG_U32*4)

static __device__ float    g_A[VMAX_TOT];
static __device__ int      g_grid[GRID_TOT];
static __device__ int      g_p2p[3*NPTS];
static __device__ int      g_vox3[3*NPTS];
static __device__ int      g_pt[3*NPTS];
static __device__ int      g_cnts[G_PAD];
static __device__ int      g_start[G_PAD];
static __device__ int      g_cur[G_PAD];
static __device__ int      g_soccp[G_PAD];
static __device__ int      g_bsum[512];
static __device__ int      g_bsum2[512];
static __device__ int      g_list[R0PAD];
static __device__ int      g_cnt;
static __device__ unsigned g_Wh[573440];
static __device__ unsigned g_Wl[573440];

struct KnnP  { int goff, P0, P1, P2; float pv0, pv1, pv2; };
struct GsP   { int M, goff, P0, P1, P2; };
struct CntP  { int ro, D0, D1, D2; float cv0, cv1, cv2; };
struct PoolP { unsigned long long voff; int ro, C, Kc, M, L, nrows, compact; };
struct GemmP { unsigned long long out_base, voff; int woff, ro, Kc, Nc, D0, D1, D2, nb, nxb, compact; };

__device__ __forceinline__ void split_tf32(float v, unsigned& hi, unsigned& lo){
    unsigned h; asm("cvt.rna.tf32.f32 %0, %1;" : "=r"(h) : "f"(v));
    float r = v - __uint_as_float(h);
    unsigned l; asm("cvt.rna.tf32.f32 %0, %1;" : "=r"(l) : "f"(r));
    hi = h; lo = l;
}
__device__ __forceinline__ void mma_tf32(float* d, const unsigned* a, const unsigned* b){
    asm volatile(
        "mma.sync.aligned.m16n8k8.row.col.f32.tf32.tf32.f32 "
        "{%0,%1,%2,%3}, {%4,%5,%6,%7}, {%8,%9}, {%0,%1,%2,%3};\n"
        : "+f"(d[0]), "+f"(d[1]), "+f"(d[2]), "+f"(d[3])
        : "r"(a[0]), "r"(a[1]), "r"(a[2]), "r"(a[3]), "r"(b[0]), "r"(b[1]));
}
__device__ __forceinline__ void cpa16(void* dst_smem, const void* src){
    unsigned d = (unsigned)__cvta_generic_to_shared(dst_smem);
    asm volatile("cp.async.cg.shared.global [%0], [%1], 16;" :: "r"(d), "l"(src));
}
__device__ __forceinline__ float4 max4(float4 a, float4 b){
    return make_float4(fmaxf(a.x,b.x), fmaxf(a.y,b.y), fmaxf(a.z,b.z), fmaxf(a.w,b.w));
}

// Slim prep: ONLY what k_gscnt needs (grid + counts init + counter).
__global__ void k_prep(){
    int stride = gridDim.x*blockDim.x;
    int tid = blockIdx.x*blockDim.x + threadIdx.x;
    for (int i = tid; i < GRID_TOT; i += stride) g_grid[i] = 0x7fffffff;
    for (int i = tid; i < G_PAD; i += stride) g_cnts[i] = 0;
    if (tid == 0) g_cnt = 0;
}

// Polar-grid scatter (y=0..2) + cartesian count (y=3..5), one launch.
__global__ void k_gscnt(const int* __restrict__ i0, const int* __restrict__ i1,
                        const int* __restrict__ i2, GsP s0, GsP s1, GsP s2,
                        const float* __restrict__ coord, CntP c0, CntP c1, CntP c2){
    int yv = blockIdx.y;
    int i = blockIdx.x*blockDim.x + threadIdx.x;
    if (yv < 3){
        const int* idx = (yv==0) ? i0 : (yv==1) ? i1 : i2;
        GsP s = (yv==0) ? s0 : (yv==1) ? s1 : s2;
        if (i >= s.M) return;
        int x = idx[i*4+1], y = idx[i*4+2], z = idx[i*4+3];
        if ((unsigned)x >= (unsigned)s.P0 || (unsigned)y >= (unsigned)s.P1 ||
            (unsigned)z >= (unsigned)s.P2) return;
        atomicMin(&g_grid[s.goff + (x*s.P1+y)*s.P2 + z], i);
    } else {
        int L = yv - 3;
        CntP c = (L==0) ? c0 : (L==1) ? c1 : c2;
        if (i >= NPTS) return;
        float fx = __fdiv_rn(coord[i*3+0] + 25.6f, c.cv0);
        float fy = __fdiv_rn(coord[i*3+1] + 25.6f, c.cv1);
        float fz = __fdiv_rn(coord[i*3+2] + 2.0f,  c.cv2);
        int x = min(max((int)floorf(fx), 0), c.D0-1);
        int y = min(max((int)floorf(fy), 0), c.D1-1);
        int z = min(max((int)floorf(fz), 0), c.D2-1);
        int lin = (x*c.D2 + z)*c.D1 + y;   // internal ordering: y fastest
        g_vox3[L*NPTS + i] = lin;
        atomicAdd(&g_cnts[c.ro + lin], 1);
    }
}

__device__ __forceinline__ void knn_check(const int* __restrict__ grid,
                                          int x,int y,int z,int qx,int qy,int qz,
                                          int P1,int P2,int& bd,int& bi){
    int c = grid[(x*P1+y)*P2 + z];
    if (c != 0x7fffffff){
        int dx = x-qx, dy = y-qy, dz = z-qz;
        int d = dx*dx + dy*dy + dz*dz;
        if (d < bd || (d == bd && c < bi)){ bd = d; bi = c; }
    }
}

// Exact 1-NN (thread-per-query), 3 levels concurrent (blockIdx.y 0..2).
// blockIdx.y == 3: co-scheduled bandwidth work (zero L0 output + split W).
__global__ void k_knn_all(const float* __restrict__ pc, KnnP q0, KnnP q1, KnnP q2,
                          float* __restrict__ out,
                          const float* __restrict__ w0, const float* __restrict__ w1,
                          const float* __restrict__ w2){
    int L = blockIdx.y;
    if (L == 3){
        const int no4 = (int)(OUT_L0_F >> 2);
        uint4 z = make_uint4(0u,0u,0u,0u);
        uint4* po = reinterpret_cast<uint4*>(out);
        int stride = gridDim.x*blockDim.x;
        int tid = blockIdx.x*blockDim.x + threadIdx.x;
        for (int i = tid; i < no4; i += stride) po[i] = z;
        for (int i = tid; i < 573440; i += stride){
            float v;
            if (i < 49152)       v = w0[i];
            else if (i < 180224) v = w1[i - 49152];
            else                 v = w2[i - 180224];
            split_tf32(v, g_Wh[i], g_Wl[i]);
        }
        return;
    }
    KnnP p = (L==0) ? q0 : (L==1) ? q1 : q2;
    int i = blockIdx.x*blockDim.x + threadIdx.x;
    if (i >= NPTS) return;
    const int* grid = g_grid + p.goff;
    int qx = (int)floorf(__fdiv_rn(pc[i*3+0]-0.0f,        p.pv0));
    int qy = (int)floorf(__fdiv_rn(pc[i*3+1]+3.14159274f, p.pv1));
    int qz = (int)floorf(__fdiv_rn(pc[i*3+2]+4.0f,        p.pv2));
    int bd = 0x7fffffff, bi = 0x7fffffff;
    int rmax = p.P0 + p.P1 + p.P2;
    for (int r = 0; r <= rmax; r++){
        if ((long long)r*r > (long long)bd) break;
        int x0 = max(qx-r, 0), x1 = min(qx+r, p.P0-1);
        int y0 = max(qy-r, 0), y1 = min(qy+r, p.P1-1);
        int z0 = max(qz-r, 0), z1 = min(qz+r, p.P2-1);
        for (int x = x0; x <= x1; x++){
            bool fx = (x == qx-r) || (x == qx+r);
            for (int y = y0; y <= y1; y++){
                bool fy = (y == qy-r) || (y == qy+r);
                if (fx | fy){
                    for (int z = z0; z <= z1; z++)
                        knn_check(grid,x,y,z,qx,qy,qz,p.P1,p.P2,bd,bi);
                } else {
                    int za = qz - r;
                    if (za >= 0 && za < p.P2) knn_check(grid,x,y,za,qx,qy,qz,p.P1,p.P2,bd,bi);
                    int zb = qz + r;
                    if (r > 0 && zb >= 0 && zb < p.P2) knn_check(grid,x,y,zb,qx,qy,qz,p.P1,p.P2,bd,bi);
                }
            }
        }
    }
    g_p2p[L*NPTS + i] = bi;
}

// Dual scan pass 1: counts prefix AND L0-occupancy prefix (no atomics).
__global__ void k_scan1(){
    __shared__ int sh[256];
    __shared__ int sh2[256];
    int b = blockIdx.x, t = threadIdx.x;
    int base = b*1024 + t*4;
    int4 v = *reinterpret_cast<int4*>(&g_cnts[base]);
    int s = v.x+v.y+v.z+v.w;
    int isL0 = (b < 256);                  // L0 region = first 262144 cells
    int o0 = (isL0 && v.x > 0) ? 1 : 0;
    int o1 = (isL0 && v.y > 0) ? 1 : 0;
    int o2 = (isL0 && v.z > 0) ? 1 : 0;
    int o3 = (isL0 && v.w > 0) ? 1 : 0;
    int so = o0+o1+o2+o3;
    sh[t] = s; sh2[t] = so;
    __syncthreads();
    #pragma unroll
    for (int off = 1; off < 256; off <<= 1){
        int val  = (t >= off) ? sh[t-off]  : 0;
        int val2 = (t >= off) ? sh2[t-off] : 0;
        __syncthreads();
        sh[t] += val; sh2[t] += val2;
        __syncthreads();
    }
    int excl = sh[t] - s;
    g_start[base]   = excl;
    g_start[base+1] = excl + v.x;
    g_start[base+2] = excl + v.x + v.y;
    g_start[base+3] = excl + v.x + v.y + v.z;
    int excl2 = sh2[t] - so;
    g_soccp[base]   = excl2;
    g_soccp[base+1] = excl2 + o0;
    g_soccp[base+2] = excl2 + o0 + o1;
    g_soccp[base+3] = excl2 + o0 + o1 + o2;
    if (t == 255){ g_bsum[b] = sh[255]; g_bsum2[b] = sh2[255]; }
}
// Dual scan pass 2: scan block sums; also publishes total L0 occupancy (g_cnt).
__global__ void k_scan2(){
    __shared__ int sh[512];
    __shared__ int sh2[512];
    int t = threadIdx.x;
    int v  = (t < 293) ? g_bsum[t]  : 0;
    int v2 = (t < 293) ? g_bsum2[t] : 0;
    sh[t] = v; sh2[t] = v2;
    __syncthreads();
    #pragma unroll
    for (int off = 1; off < 512; off <<= 1){
        int x  = (t >= off) ? sh[t-off]  : 0;
        int x2 = (t >= off) ? sh2[t-off] : 0;
        __syncthreads();
        sh[t] += x; sh2[t] += x2;
        __syncthreads();
    }
    if (t < 293){ g_bsum[t] = sh[t] - v; g_bsum2[t] = sh2[t] - v2; }
    if (t == 292) g_cnt = sh2[292];        // total occupied L0 voxels (deterministic)
}
// Pass 3: finalize start/cur; write L0 compact list from scanned prefixes.
__global__ void k_scan3(){
    int b = blockIdx.x, t = threadIdx.x;
    int add = g_bsum[b];
    int base = b*1024 + t*4;
    int4 v = *reinterpret_cast<int4*>(&g_start[base]);
    v.x += add; v.y += add; v.z += add; v.w += add;
    *reinterpret_cast<int4*>(&g_start[base]) = v;
    *reinterpret_cast<int4*>(&g_cur[base])   = v;
    if (b < 256){
        int add2 = g_bsum2[b];
        int4 c  = *reinterpret_cast<int4*>(&g_cnts[base]);
        int4 sp = *reinterpret_cast<int4*>(&g_soccp[base]);
        if (c.x > 0) g_list[sp.x + add2] = base;
        if (c.y > 0) g_list[sp.y + add2] = base + 1;
        if (c.z > 0) g_list[sp.z + add2] = base + 2;
        if (c.w > 0) g_list[sp.w + add2] = base + 3;
    }
}

__global__ void k_ptscatter_all(){
    int L = blockIdx.y;
    int ro = (L==0) ? RO0 : (L==1) ? RO1 : RO2;
    int i = blockIdx.x*blockDim.x + threadIdx.x;
    if (i >= NPTS) return;
    int lin = g_vox3[L*NPTS + i];
    int pos = atomicAdd(&g_cur[ro + lin], 1);
    g_pt[pos] = i;
}

// Gather-based max pooling (proven block-per-voxel shape); output written as
// PLAIN FLOAT (split to tf32 moved into the GEMM fragment load — halves the
// pool write traffic and the GEMM A read traffic).
__global__ void __launch_bounds__(128)
k_pool_all(const float* __restrict__ pf,
           const float* __restrict__ vf0, const float* __restrict__ vf1,
           const float* __restrict__ vf2,
           PoolP p0, PoolP p1, PoolP p2){
    int b = blockIdx.x;
    PoolP p; const float* vf;
    if (b < p0.nrows){ p = p0; vf = vf0; }
    else if (b < p0.nrows + p1.nrows){ p = p1; vf = vf1; b -= p0.nrows; }
    else { p = p2; vf = vf2; b -= p0.nrows + p1.nrows; }
    int row = b, lin;
    if (p.compact){
        if (row >= g_cnt) return;
        lin = g_list[row];
    } else lin = row;
    int s0 = g_start[p.ro + lin], s1 = g_start[p.ro + lin + 1];
    int n = s1 - s0;
    if (n <= 0) return;
    __shared__ int sp[128], spp[128];
    int t = threadIdx.x;
    const float4* pf4 = reinterpret_cast<const float4*>(pf);
    const float4* vf4 = reinterpret_cast<const float4*>(vf);
    int C4 = p.C >> 2;
    int K4 = p.Kc >> 2;                    // 96 / 128 / 192
    float4 m[2];
    float ninf = -__int_as_float(0x7f800000);
    m[0] = make_float4(ninf, ninf, ninf, ninf);
    m[1] = m[0];
    for (int c0 = 0; c0 < n; c0 += 128){
        int nc = min(128, n - c0);
        __syncthreads();
        if (t < nc){
            int i = g_pt[s0 + c0 + t];
            sp[t] = i;
            int pp = g_p2p[p.L*NPTS + i];
            spp[t] = ((unsigned)pp < (unsigned)p.M) ? pp : 0;
        }
        __syncthreads();
        int j = 0;
        for (; j + 2 <= nc; j += 2){
            int ia = sp[j],   pa = spp[j];
            int ib = sp[j+1], pb = spp[j+1];
            int q = 0;
            for (int kq = t; kq < K4; kq += 128, q++){
                float4 a = (kq < 64) ? pf4[(size_t)ia*64 + kq]
                                     : vf4[(size_t)pa*C4 + (kq-64)];
                float4 c = (kq < 64) ? pf4[(size_t)ib*64 + kq]
                                     : vf4[(size_t)pb*C4 + (kq-64)];
                m[q] = max4(m[q], max4(a, c));
            }
        }
        if (j < nc){
            int ia = sp[j], pa = spp[j];
            int q = 0;
            for (int kq = t; kq < K4; kq += 128, q++){
                float4 a = (kq < 64) ? pf4[(size_t)ia*64 + kq]
                                     : vf4[(size_t)pa*C4 + (kq-64)];
                m[q] = max4(m[q], a);
            }
        }
    }
    size_t rb = p.voff + (size_t)row * (size_t)p.Kc;
    int q = 0;
    for (int kq = t; kq < K4; kq += 128, q++)
        *reinterpret_cast<float4*>(&g_A[rb + kq*4]) = m[q];
}

// Split-TF32 tensor-core GEMM, cp.async double-buffered; A arrives as float
// and is split to tf32 hi/lo IN REGISTERS at fragment load (identical values
// and mma order as before -> same numerics). B remains pre-split.
__global__ void __launch_bounds__(256, 2)
k_gemm_all(const float* __restrict__ b0, const float* __restrict__ b1,
           const float* __restrict__ b2, float* __restrict__ out,
           GemmP q0, GemmP q1, GemmP q2){
    extern __shared__ unsigned dyn[];
    int b = blockIdx.x;
    GemmP p; const float* bias;
    if (b < q0.nb){ p = q0; bias = b0; }
    else if (b < q0.nb + q1.nb){ p = q1; bias = b1; b -= q0.nb; }
    else { p = q2; bias = b2; b -= q0.nb + q1.nb; }
    int bx = b % p.nxb, by = b / p.nxb;
    int row0 = bx * 128;
    int cnt = 0;
    if (p.compact){
        cnt = *(volatile int*)&g_cnt;
        if (row0 >= cnt) return;
    }
    __shared__ int s_ob[128];
    __shared__ int s_oc[128];

    int t = threadIdx.x;
    int lane = t & 31, wid = t >> 5;
    int warp_m = wid & 1, warp_n = wid >> 1;
    int g = lane >> 2, tg = lane & 3;
    int col0 = by * 128;
    const float* gA = g_A + p.voff + (size_t)row0 * (size_t)p.Kc;
    const unsigned* Whb = g_Wh + p.woff;
    const unsigned* Wlb = g_Wl + p.woff;
    int niter = p.Kc >> 4;

    auto stage_fill = [&](int s, int k0){
        unsigned* S  = dyn + s*STG_U32;
        float*    Af = reinterpret_cast<float*>(S);
        unsigned* Bh = S + 2560;
        unsigned* Bl = S + 4736;
        {
            int seg = t + 256;                 // two segments: t and t+256
            int m0  = t >> 1,  s0i = (t   & 1) << 3;   // 8-float halves? no — keep 16B quads
            (void)seg; (void)m0; (void)s0i;
        }
        #pragma unroll
        for (int j = 0; j < 2; j++){
            int seg = t + j*256;               // 0..511 -> 128 rows x 4 quads
            int m   = seg >> 2;
            int si  = (seg & 3) << 2;
            size_t go = (size_t)m*p.Kc + k0 + si;
            cpa16(Af + m*20 + si, gA + go);
        }
        #pragma unroll
        for (int j = 0; j < 2; j++){
            int seg = t + j*256;
            int kk  = seg >> 5;
            int n4  = (seg & 31) << 2;
            size_t go = (size_t)(k0+kk)*p.Nc + col0 + n4;
            cpa16(Bh + kk*136 + n4, Whb + go);
            cpa16(Bl + kk*136 + n4, Wlb + go);
        }
    };

    float acc[4][4][4];
    #pragma unroll
    for (int a = 0; a < 4; a++)
        #pragma unroll
        for (int c = 0; c < 4; c++)
            #pragma unroll
            for (int d = 0; d < 4; d++) acc[a][c][d] = 0.0f;

    stage_fill(0, 0);
    asm volatile("cp.async.commit_group;");

    for (int it = 0; it < niter; it++){
        int nxt = it + 1;
        if (nxt < niter) stage_fill(nxt & 1, nxt << 4);
        asm volatile("cp.async.commit_group;");
        asm volatile("cp.async.wait_group 1;");
        __syncthreads();

        unsigned* S  = dyn + (it & 1)*STG_U32;
        float*    Af = reinterpret_cast<float*>(S);
        unsigned* Bh = S + 2560;
        unsigned* Bl = S + 4736;
        #pragma unroll
        for (int ks = 0; ks < 2; ks++){
            int kk = ks << 3;
            unsigned bhf[4][2], blf[4][2];
            #pragma unroll
            for (int nt = 0; nt < 4; nt++){
                int n = warp_n*32 + nt*8 + g;
                bhf[nt][0] = Bh[(kk+tg)*136 + n];
                bhf[nt][1] = Bh[(kk+tg+4)*136 + n];
                blf[nt][0] = Bl[(kk+tg)*136 + n];
                blf[nt][1] = Bl[(kk+tg+4)*136 + n];
            }
            #pragma unroll
            for (int mt = 0; mt < 4; mt++){
                int r0 = warp_m*64 + mt*16 + g;
                float af[4];
                af[0] = Af[(r0  )*20 + kk+tg];
                af[1] = Af[(r0+8)*20 + kk+tg];
                af[2] = Af[(r0  )*20 + kk+tg+4];
                af[3] = Af[(r0+8)*20 + kk+tg+4];
                unsigned ahf[4], alf[4];
                #pragma unroll
                for (int q = 0; q < 4; q++) split_tf32(af[q], ahf[q], alf[q]);
                #pragma unroll
                for (int nt = 0; nt < 4; nt++){
                    mma_tf32(acc[mt][nt], ahf, bhf[nt]);
                    mma_tf32(acc[mt][nt], ahf, blf[nt]);
                    mma_tf32(acc[mt][nt], alf, bhf[nt]);
                }
            }
        }
        __syncthreads();
    }

    if (t < 128){
        int v = row0 + t;
        int lin = p.compact ? g_list[v] : v;
        int y  = lin % p.D1;
        int q  = lin / p.D1;
        int zz = q % p.D2;
        int xx = q / p.D2;
        s_ob[t] = (zz*p.D0 + xx)*p.D1 + y;
        s_oc[t] = p.compact ? (v < cnt) : (g_cnts[p.ro + v] > 0);
    }
    __syncthreads();

    size_t cstride = (size_t)p.D2 * p.D0 * p.D1;
    float* stage = reinterpret_cast<float*>(dyn);
    #pragma unroll
    for (int s = 0; s < 4; s++){
        if (warp_n == s){
            #pragma unroll
            for (int mt = 0; mt < 4; mt++){
                int r0 = warp_m*64 + mt*16 + g;
                int r1 = r0 + 8;
                int oc0 = s_oc[r0], oc1 = s_oc[r1];
                #pragma unroll
                for (int nt = 0; nt < 4; nt++){
                    int cb = nt*8 + 2*tg;
                    float bv0 = bias[col0 + s*32 + cb];
                    float bv1 = bias[col0 + s*32 + cb + 1];
                    stage[(cb  )*132 + r0] = oc0 ? fmaxf(acc[mt][nt][0] + bv0, 0.0f) : 0.0f;
                    stage[(cb+1)*132 + r0] = oc0 ? fmaxf(acc[mt][nt][1] + bv1, 0.0f) : 0.0f;
                    stage[(cb  )*132 + r1] = oc1 ? fmaxf(acc[mt][nt][2] + bv0, 0.0f) : 0.0f;
                    stage[(cb+1)*132 + r1] = oc1 ? fmaxf(acc[mt][nt][3] + bv1, 0.0f) : 0.0f;
                }
            }
        }
        __syncthreads();
        #pragma unroll
        for (int j = 0; j < 16; j++){
            int e  = t + j*256;
            int cc = e >> 7;
            int rr = e & 127;
            int c  = col0 + (s << 5) + cc;
            if (!p.compact || s_oc[rr])
                out[p.out_base + (size_t)c*cstride + s_ob[rr]] = stage[cc*132 + rr];
        }
        __syncthreads();
    }
}

extern "C" void kernel_launch(void* const* d_in, const int* in_sizes, int n_in,
                              void* d_out, int out_size){
    (void)in_sizes; (void)n_in; (void)out_size;
    const float* point_feat = (const float*)d_in[0];
    const float* p_coord    = (const float*)d_in[1];
    const float* coord      = (const float*)d_in[2];
    const int*   idxs[3] = {(const int*)d_in[4],  (const int*)d_in[8],  (const int*)d_in[12]};
    const float* vfs[3]  = {(const float*)d_in[5],(const float*)d_in[9],(const float*)d_in[13]};
    const float* Ws[3]   = {(const float*)d_in[6],(const float*)d_in[10],(const float*)d_in[14]};
    const float* bs[3]   = {(const float*)d_in[7],(const float*)d_in[11],(const float*)d_in[15]};
    float* out = (float*)d_out;

    const int Ms[3]  = {40000, 15000, 5000};
    const int Cs[3]  = {128, 256, 512};
    const int P0s[3] = {240, 120, 60}, P1s[3] = {180, 90, 45}, P2s[3] = {16, 8, 4};
    const int D0s[3] = {128, 64, 32},  D1s[3] = {128, 64, 32}, D2s[3] = {16, 8, 4};
    const int goffs[3] = {GOFF0, GOFF1, GOFF2};
    const int ros[3]   = {RO0, RO1, RO2};
    const int woffs[3] = {0, 49152, 180224};
    const size_t voffs[3] = {OFF_L0, OFF_L1, OFF_L2};
    const int nrows[3] = {R0PAD, 32768, 4096};

    const float pi  = 3.14159265358979f;
    const float r0c = 50.0f, r1c = pi + pi, r2c = 6.0f;
    const float cr0 = 25.6f + 25.6f, cr1 = cr0, cr2 = 4.4f + 2.0f;

    KnnP kp[3]; GsP gp[3]; CntP cp[3]; PoolP pp[3]; GemmP gm[3];
    size_t base = 0;
    for (int L = 0; L < 3; L++){
        float sf = (float)(2 << L);
        kp[L].goff = goffs[L];
        kp[L].P0 = P0s[L]; kp[L].P1 = P1s[L]; kp[L].P2 = P2s[L];
        kp[L].pv0 = r0c / (479.0f / sf);
        kp[L].pv1 = r1c / (359.0f / sf);
        kp[L].pv2 = r2c / (31.0f  / sf);
        gp[L].M = Ms[L]; gp[L].goff = goffs[L];
        gp[L].P0 = P0s[L]; gp[L].P1 = P1s[L]; gp[L].P2 = P2s[L];
        cp[L].ro = ros[L];
        cp[L].D0 = D0s[L]; cp[L].D1 = D1s[L]; cp[L].D2 = D2s[L];
        cp[L].cv0 = cr0 / (float)D0s[L];
        cp[L].cv1 = cr1 / (float)D1s[L];
        cp[L].cv2 = cr2 / (float)D2s[L];
        pp[L].voff = voffs[L]; pp[L].ro = ros[L];
        pp[L].C = Cs[L]; pp[L].Kc = 256 + Cs[L]; pp[L].M = Ms[L];
        pp[L].L = L; pp[L].nrows = nrows[L]; pp[L].compact = (L == 0);
        gm[L].out_base = base; gm[L].voff = voffs[L];
        gm[L].woff = woffs[L]; gm[L].ro = ros[L];
        gm[L].Kc = 256 + Cs[L]; gm[L].Nc = Cs[L];
        gm[L].D0 = D0s[L]; gm[L].D1 = D1s[L]; gm[L].D2 = D2s[L];
        gm[L].nxb = nrows[L] / 128;
        gm[L].nb  = gm[L].nxb * (Cs[L] / 128);
        gm[L].compact = (L == 0);
        base += (size_t)Cs[L] * D2s[L] * D0s[L] * D1s[L];
    }

    cudaFuncSetAttribute(k_gemm_all, cudaFuncAttributeMaxDynamicSharedMemorySize,
                         GEMM_SMEM_B);

    k_prep<<<512, 256>>>();
    k_gscnt<<<dim3((NPTS+255)/256, 6), 256>>>(idxs[0], idxs[1], idxs[2],
                                              gp[0], gp[1], gp[2],
                                              coord, cp[0], cp[1], cp[2]);
    // KNN (y=0..2, thread-per-query) + co-scheduled zero/splitW (y=3)
    k_knn_all<<<dim3((NPTS+127)/128, 4), 128>>>(p_coord, kp[0], kp[1], kp[2],
                                                out, Ws[0], Ws[1], Ws[2]);
    k_scan1<<<293, 256>>>();
    k_scan2<<<1, 512>>>();
    k_scan3<<<293, 256>>>();
    k_ptscatter_all<<<dim3((NPTS+255)/256, 3), 256>>>();

    int pool_blocks = nrows[0] + nrows[1] + nrows[2];
    k_pool_all<<<pool_blocks, 128>>>(point_feat, vfs[0], vfs[1], vfs[2],
                                     pp[0], pp[1], pp[2]);
    int gemm_blocks = gm[0].nb + gm[1].nb + gm[2].nb;
    k_gemm_all<<<gemm_blocks, 256, GEMM_SMEM_B>>>(bs[0], bs[1], bs[2], out,
                                                  gm[0], gm[1], gm[2]);
}